// round 3
// baseline (speedup 1.0000x reference)
#include <cuda_runtime.h>
#include <math.h>

typedef unsigned long long u64;

// ---- problem dims ----
#define NB      32
#define NUMPTS  2048
#define PN      1024
#define KK      16
#define CIN     64
#define CHALF   64
#define CMID    32
#define CCAT    96
#define COUT    128
#define TILEP   8
#define FCS     100
#define BNI     0.9999950000374996f

// scratch
__device__ float g_ftsl[NB * NUMPTS * CHALF];
__device__ float g_xd1Wd[256 * 512];   // dup: [j][2q],(2q+1) = xd1W[j][q]
__device__ float g_xd2Wd[256 * 512];
__device__ float g_xcWd [256 * 96];    // dup: [q][2k],(2k+1) = xcW[q][k48]
__device__ float g_dwWd [96 * 32];     // interleave: [c][k][2] = (dwW[c][0][k], dwW[c][1][k])

__device__ __forceinline__ float eluf(float x) {
    return x > 0.0f ? x : expm1f(x);
}
__device__ __forceinline__ u64 fma2(u64 a, u64 b, u64 c) {
    u64 d; asm("fma.rn.f32x2 %0,%1,%2,%3;" : "=l"(d) : "l"(a), "l"(b), "l"(c)); return d;
}
__device__ __forceinline__ u64 add2(u64 a, u64 b) {
    u64 d; asm("add.rn.f32x2 %0,%1,%2;" : "=l"(d) : "l"(a), "l"(b)); return d;
}
__device__ __forceinline__ u64 dup2(float x) {
    u64 d; asm("mov.b64 %0,{%1,%1};" : "=l"(d) : "f"(x)); return d;
}
__device__ __forceinline__ float2 unpk(u64 v) {
    float2 r; asm("mov.b64 {%0,%1},%2;" : "=f"(r.x), "=f"(r.y) : "l"(v)); return r;
}

// ============================================================================
// Prep: duplicate / interleave weights for packed-f32x2 consumption
// ============================================================================
__global__ void __launch_bounds__(256) dup_weights(
    const float* __restrict__ xd1W, const float* __restrict__ xd2W,
    const float* __restrict__ xcW,  const float* __restrict__ dwW)
{
    int idx = blockIdx.x * 256 + threadIdx.x;      // 0..65535
    int j = idx >> 8, q = idx & 255;
    float w1 = xd1W[idx];
    g_xd1Wd[j * 512 + 2 * q] = w1; g_xd1Wd[j * 512 + 2 * q + 1] = w1;
    float w2 = xd2W[idx];
    g_xd2Wd[j * 512 + 2 * q] = w2; g_xd2Wd[j * 512 + 2 * q + 1] = w2;
    if (idx < 256 * 48) {
        int qq = idx / 48, k = idx % 48;
        float w = xcW[idx];
        g_xcWd[qq * 96 + 2 * k] = w; g_xcWd[qq * 96 + 2 * k + 1] = w;
    }
    if (idx < 96 * 16) {
        int c = idx >> 4, k = idx & 15;
        g_dwWd[(c * 16 + k) * 2]     = dwW[c * 32 + k];
        g_dwWd[(c * 16 + k) * 2 + 1] = dwW[c * 32 + 16 + k];
    }
}

// ============================================================================
// Kernel A: dense0 (packed f32x2)
// ============================================================================
__global__ void __launch_bounds__(256) dense0_kernel(
    const float* __restrict__ fts, const float* __restrict__ W,
    const float* __restrict__ b,   const float* __restrict__ g,
    const float* __restrict__ be)
{
    __shared__ float Ws[64 * 64];
    __shared__ float xs[16 * 64];
    const int t = threadIdx.x;
    const size_t row0 = (size_t)blockIdx.x * 16;

#pragma unroll
    for (int u = 0; u < 16; u++) Ws[t + 256 * u] = W[t + 256 * u];
    ((float4*)xs)[t] = ((const float4*)(fts + row0 * 64))[t];
    __syncthreads();

    const int r  = t >> 4;
    const int cb = (t & 15) * 4;
    u64 a0 = 0ull, a1 = 0ull;
#pragma unroll 8
    for (int k = 0; k < 64; k++) {
        u64 xd = dup2(xs[r * 64 + k]);
        ulonglong2 w = *(const ulonglong2*)&Ws[k * 64 + cb];
        a0 = fma2(xd, w.x, a0);
        a1 = fma2(xd, w.y, a1);
    }
    float2 f0 = unpk(a0), f1 = unpk(a1);
    float4 b4 = *(const float4*)&b[cb];
    float4 g4 = *(const float4*)&g[cb];
    float4 e4 = *(const float4*)&be[cb];
    float4 o;
    o.x = g4.x * (eluf(f0.x + b4.x) * BNI) + e4.x;
    o.y = g4.y * (eluf(f0.y + b4.y) * BNI) + e4.y;
    o.z = g4.z * (eluf(f1.x + b4.z) * BNI) + e4.z;
    o.w = g4.w * (eluf(f1.y + b4.w) * BNI) + e4.w;
    *(float4*)&g_ftsl[(row0 + r) * 64 + cb] = o;
}

// ============================================================================
// Kernel B: fused XConv, packed f32x2.
// smem (floats):
//   PT    [48][8]        @ 0      (pls transposed)
//   XA    [256][8]       @ 384    |  HD [32][256] spans 384..8576 during E
//   XB    [256][8]       @ 2432   |
//   XD    4096           @ 4480   (RED partials in C/D, X2dup in D/F, DWSdup in G)
//   FC    [8][16][FCS]   @ 8576   (12800)
//   SIDX  @ 21376 (128)
//   SD1W @21504(96) SD1B @21600 SD1G @21632 SD1BE @21664
//   SD2W @21696(1024) SD2B @22720 SD2G @22752 SD2BE @22784
// total 22816 floats = 91264 B
// ============================================================================
#define SM_FLOATS 22816
#define SMEM_B    (SM_FLOATS * 4)

__global__ void __launch_bounds__(256, 2) xconv_kernel(
    const float* __restrict__ rep_pts, const float* __restrict__ pts,
    const int*   __restrict__ pts_idx,
    const float* __restrict__ d1W, const float* __restrict__ d1b,
    const float* __restrict__ d1g, const float* __restrict__ d1be,
    const float* __restrict__ d2W, const float* __restrict__ d2b,
    const float* __restrict__ d2g, const float* __restrict__ d2be,
    const float* __restrict__ xcb,
    const float* __restrict__ xd1b, const float* __restrict__ xd2b,
    const float* __restrict__ dwb,
    const float* __restrict__ pwW,  const float* __restrict__ pwb,
    const float* __restrict__ endg, const float* __restrict__ endbe,
    float* __restrict__ out)
{
    extern __shared__ float sm[];
    float* PT   = sm;            // [48][8]
    float* XA   = sm + 384;
    float* XB   = sm + 2432;
    float* HD   = sm + 384;      // [32][256] dup
    float* XD   = sm + 4480;     // RED / X2dup / DWSdup
    float* FC   = sm + 8576;
    int*   SIDX = (int*)(sm + 21376);
    float* SD1W = sm + 21504; float* SD1B  = sm + 21600;
    float* SD1G = sm + 21632; float* SD1BE = sm + 21664;
    float* SD2W = sm + 21696; float* SD2B  = sm + 22720;
    float* SD2G = sm + 22752; float* SD2BE = sm + 22784;

    const int t   = threadIdx.x;
    const int gp0 = blockIdx.x * TILEP;
    const int n   = gp0 >> 10;

    // ---- phase 0: small weights + indices ----
    for (int u = t; u < 96 + 1024; u += 256) {
        if (u < 96) SD1W[u] = d1W[u];
        else        SD2W[u - 96] = d2W[u - 96];
    }
    if (t < 32) {
        SD1B[t] = d1b[t]; SD1G[t] = d1g[t]; SD1BE[t] = d1be[t];
        SD2B[t] = d2b[t]; SD2G[t] = d2g[t]; SD2BE[t] = d2be[t];
    }
    if (t < 128) SIDX[t] = pts_idx[(size_t)gp0 * 16 + t];
    __syncthreads();

    // ---- gather: PT (transposed local coords) + FC[:,32:96] ----
    if (t < 128) {
        int i = t >> 4, k = t & 15;
        int gi = SIDX[t];
        const float* pp = pts + ((size_t)n * NUMPTS + gi) * 3;
        const float* rp = rep_pts + (size_t)(gp0 + i) * 3;
        PT[( 0 + k) * 8 + i] = pp[0] - rp[0];
        PT[(16 + k) * 8 + i] = pp[1] - rp[1];
        PT[(32 + k) * 8 + i] = pp[2] - rp[2];
    }
    {
        int row = t >> 1, half = t & 1;
        int gi = SIDX[row];
        const float4* src = (const float4*)(g_ftsl + ((size_t)n * NUMPTS + gi) * 64 + half * 32);
        float4* dst = (float4*)&FC[row * FCS + 32 + half * 32];
#pragma unroll
        for (int u = 0; u < 8; u++) dst[u] = src[u];
    }
    __syncthreads();

    // ---- E1: dense1 (3->32) -> HD duplicated [c][2*row] ----
    {
        const int row = t & 127, hc = t >> 7;
        const int i = row >> 4, k = row & 15;
        float px = PT[k * 8 + i];
        float py = PT[(16 + k) * 8 + i];
        float pz = PT[(32 + k) * 8 + i];
#pragma unroll
        for (int u = 0; u < 16; u++) {
            int c = hc * 16 + u;
            float v = fmaf(px, SD1W[c], fmaf(py, SD1W[32 + c],
                      fmaf(pz, SD1W[64 + c], SD1B[c])));
            float h = SD1G[c] * (eluf(v) * BNI) + SD1BE[c];
            *(u64*)&HD[c * 256 + 2 * row] = dup2(h);
        }
    }
    __syncthreads();

    // ---- E2: dense2 (32->32) -> FC[:,0:32] ----
    {
        const int row = t & 127, hc = t >> 7;
        u64 acc[8];
        {
            ulonglong2 b0 = *(const ulonglong2*)&SD2B[hc * 16];
            ulonglong2 b1 = *(const ulonglong2*)&SD2B[hc * 16 + 4];
            ulonglong2 b2 = *(const ulonglong2*)&SD2B[hc * 16 + 8];
            ulonglong2 b3 = *(const ulonglong2*)&SD2B[hc * 16 + 12];
            acc[0] = b0.x; acc[1] = b0.y; acc[2] = b1.x; acc[3] = b1.y;
            acc[4] = b2.x; acc[5] = b2.y; acc[6] = b3.x; acc[7] = b3.y;
        }
#pragma unroll 4
        for (int c = 0; c < 32; c++) {
            u64 hd = *(const u64*)&HD[c * 256 + 2 * row];
            const ulonglong2* w = (const ulonglong2*)&SD2W[c * 32 + hc * 16];
            ulonglong2 w0 = w[0], w1 = w[1], w2 = w[2], w3 = w[3];
            acc[0] = fma2(hd, w0.x, acc[0]); acc[1] = fma2(hd, w0.y, acc[1]);
            acc[2] = fma2(hd, w1.x, acc[2]); acc[3] = fma2(hd, w1.y, acc[3]);
            acc[4] = fma2(hd, w2.x, acc[4]); acc[5] = fma2(hd, w2.y, acc[5]);
            acc[6] = fma2(hd, w3.x, acc[6]); acc[7] = fma2(hd, w3.y, acc[7]);
        }
#pragma unroll
        for (int u = 0; u < 8; u++) {
            int c2 = hc * 16 + 2 * u;
            float2 f = unpk(acc[u]);
            float o0 = SD2G[c2]     * (eluf(f.x) * BNI) + SD2BE[c2];
            float o1 = SD2G[c2 + 1] * (eluf(f.y) * BNI) + SD2BE[c2 + 1];
            float2 st; st.x = o0; st.y = o1;
            *(float2*)&FC[row * FCS + c2] = st;
        }
    }
    __syncthreads();   // HD region reused as XA next

    // ---- Phase B: X0 = elu(pls @ xcW^T + b) -> XA[q][i] ----
    {
        const int q = t;
        u64 acc[4] = {0ull, 0ull, 0ull, 0ull};
        for (int kt = 0; kt < 48; kt += 4) {
            u64 wd[4];
#pragma unroll
            for (int u = 0; u < 4; u++)
                wd[u] = *(const u64*)&g_xcWd[q * 96 + 2 * (kt + u)];
#pragma unroll
            for (int u = 0; u < 4; u++) {
                ulonglong2 a0 = *(const ulonglong2*)&PT[(kt + u) * 8];
                ulonglong2 a1 = *(const ulonglong2*)&PT[(kt + u) * 8 + 4];
                acc[0] = fma2(a0.x, wd[u], acc[0]);
                acc[1] = fma2(a0.y, wd[u], acc[1]);
                acc[2] = fma2(a1.x, wd[u], acc[2]);
                acc[3] = fma2(a1.y, wd[u], acc[3]);
            }
        }
        float b = xcb[q];
        float2 f0 = unpk(acc[0]), f1 = unpk(acc[1]);
        float2 f2 = unpk(acc[2]), f3 = unpk(acc[3]);
        float4 o0, o1;
        o0.x = eluf(f0.x + b); o0.y = eluf(f0.y + b);
        o0.z = eluf(f1.x + b); o0.w = eluf(f1.y + b);
        o1.x = eluf(f2.x + b); o1.y = eluf(f2.y + b);
        o1.z = eluf(f3.x + b); o1.w = eluf(f3.y + b);
        *(float4*)&XA[q * 8]     = o0;
        *(float4*)&XA[q * 8 + 4] = o1;
    }
    __syncthreads();

    // ---- Phase C: X1 = elu(X0 @ xd1W + b), split-j + reduction ----
    {
        const int qp = t & 127, jh = t >> 7;
        const int jb = jh * 128;
        u64 acc[8];
#pragma unroll
        for (int m = 0; m < 8; m++) acc[m] = 0ull;
        for (int jt = 0; jt < 128; jt += 4) {
            ulonglong2 wd[4];
#pragma unroll
            for (int u = 0; u < 4; u++)
                wd[u] = *(const ulonglong2*)&g_xd1Wd[(jb + jt + u) * 512 + 4 * qp];
#pragma unroll
            for (int u = 0; u < 4; u++) {
                ulonglong2 a0 = *(const ulonglong2*)&XA[(jb + jt + u) * 8];
                ulonglong2 a1 = *(const ulonglong2*)&XA[(jb + jt + u) * 8 + 4];
                acc[0] = fma2(a0.x, wd[u].x, acc[0]);
                acc[1] = fma2(a0.y, wd[u].x, acc[1]);
                acc[2] = fma2(a1.x, wd[u].x, acc[2]);
                acc[3] = fma2(a1.y, wd[u].x, acc[3]);
                acc[4] = fma2(a0.x, wd[u].y, acc[4]);
                acc[5] = fma2(a0.y, wd[u].y, acc[5]);
                acc[6] = fma2(a1.x, wd[u].y, acc[6]);
                acc[7] = fma2(a1.y, wd[u].y, acc[7]);
            }
        }
        // partials -> XD: thread t owns floats [t*16, t*16+16)
        ulonglong2 s;
        s.x = acc[0]; s.y = acc[1]; *(ulonglong2*)&XD[t * 16]      = s;
        s.x = acc[2]; s.y = acc[3]; *(ulonglong2*)&XD[t * 16 + 4]  = s;
        s.x = acc[4]; s.y = acc[5]; *(ulonglong2*)&XD[t * 16 + 8]  = s;
        s.x = acc[6]; s.y = acc[7]; *(ulonglong2*)&XD[t * 16 + 12] = s;
    }
    __syncthreads();
    {
        const int q = t, qp = q >> 1, hf = q & 1;
        const int base = qp * 16 + hf * 8;
        ulonglong2 pa = *(const ulonglong2*)&XD[base];
        ulonglong2 pb = *(const ulonglong2*)&XD[base + 4];
        ulonglong2 pc = *(const ulonglong2*)&XD[2048 + base];
        ulonglong2 pd = *(const ulonglong2*)&XD[2048 + base + 4];
        u64 s0 = add2(pa.x, pc.x), s1 = add2(pa.y, pc.y);
        u64 s2 = add2(pb.x, pd.x), s3 = add2(pb.y, pd.y);
        float b = xd1b[q];
        float2 f0 = unpk(s0), f1 = unpk(s1), f2 = unpk(s2), f3 = unpk(s3);
        float4 o0, o1;
        o0.x = eluf(f0.x + b); o0.y = eluf(f0.y + b);
        o0.z = eluf(f1.x + b); o0.w = eluf(f1.y + b);
        o1.x = eluf(f2.x + b); o1.y = eluf(f2.y + b);
        o1.z = eluf(f3.x + b); o1.w = eluf(f3.y + b);
        *(float4*)&XB[q * 8]     = o0;
        *(float4*)&XB[q * 8 + 4] = o1;
    }
    __syncthreads();

    // ---- Phase D: X2 = X1 @ xd2W + b, split-j; store dup+swizzle to XD ----
    {
        const int qp = t & 127, jh = t >> 7;
        const int jb = jh * 128;
        u64 acc[8];
#pragma unroll
        for (int m = 0; m < 8; m++) acc[m] = 0ull;
        for (int jt = 0; jt < 128; jt += 4) {
            ulonglong2 wd[4];
#pragma unroll
            for (int u = 0; u < 4; u++)
                wd[u] = *(const ulonglong2*)&g_xd2Wd[(jb + jt + u) * 512 + 4 * qp];
#pragma unroll
            for (int u = 0; u < 4; u++) {
                ulonglong2 a0 = *(const ulonglong2*)&XB[(jb + jt + u) * 8];
                ulonglong2 a1 = *(const ulonglong2*)&XB[(jb + jt + u) * 8 + 4];
                acc[0] = fma2(a0.x, wd[u].x, acc[0]);
                acc[1] = fma2(a0.y, wd[u].x, acc[1]);
                acc[2] = fma2(a1.x, wd[u].x, acc[2]);
                acc[3] = fma2(a1.y, wd[u].x, acc[3]);
                acc[4] = fma2(a0.x, wd[u].y, acc[4]);
                acc[5] = fma2(a0.y, wd[u].y, acc[5]);
                acc[6] = fma2(a1.x, wd[u].y, acc[6]);
                acc[7] = fma2(a1.y, wd[u].y, acc[7]);
            }
        }
        ulonglong2 s;
        s.x = acc[0]; s.y = acc[1]; *(ulonglong2*)&XD[t * 16]      = s;
        s.x = acc[2]; s.y = acc[3]; *(ulonglong2*)&XD[t * 16 + 4]  = s;
        s.x = acc[4]; s.y = acc[5]; *(ulonglong2*)&XD[t * 16 + 8]  = s;
        s.x = acc[6]; s.y = acc[7]; *(ulonglong2*)&XD[t * 16 + 12] = s;
    }
    __syncthreads();
    float x2v[8];
    {
        const int q = t, qp = q >> 1, hf = q & 1;
        const int base = qp * 16 + hf * 8;
        ulonglong2 pa = *(const ulonglong2*)&XD[base];
        ulonglong2 pb = *(const ulonglong2*)&XD[base + 4];
        ulonglong2 pc = *(const ulonglong2*)&XD[2048 + base];
        ulonglong2 pd = *(const ulonglong2*)&XD[2048 + base + 4];
        float b = xd2b[q];
        float2 f;
        f = unpk(add2(pa.x, pc.x)); x2v[0] = f.x + b; x2v[1] = f.y + b;
        f = unpk(add2(pa.y, pc.y)); x2v[2] = f.x + b; x2v[3] = f.y + b;
        f = unpk(add2(pb.x, pd.x)); x2v[4] = f.x + b; x2v[5] = f.y + b;
        f = unpk(add2(pb.y, pd.y)); x2v[6] = f.x + b; x2v[7] = f.y + b;
    }
    __syncthreads();   // all RED reads done before X2dup writes
    {
        const int q = t, r = q >> 4, k = q & 15;
        const int off = r * 32 + 2 * ((k + r) & 15);   // bank swizzle
#pragma unroll
        for (int i = 0; i < 8; i++)
            *(u64*)&XD[i * 512 + off] = dup2(x2v[i]);
    }
    __syncthreads();

    // ---- Phase F: fts_X = X2(16x16) @ FC(16x96), in place, col-pairs ----
    {
        const int i = t >> 5, lane = t & 31;
#pragma unroll
        for (int pass = 0; pass < 2; pass++) {
            int cp = lane + pass * 32;
            if (cp < 48) {
                u64 fp[16];
#pragma unroll
                for (int k = 0; k < 16; k++)
                    fp[k] = *(const u64*)&FC[(i * 16 + k) * FCS + 2 * cp];
#pragma unroll
                for (int r = 0; r < 16; r++) {
                    u64 acc = 0ull;
#pragma unroll
                    for (int k = 0; k < 16; k++) {
                        u64 ad = *(const u64*)&XD[i * 512 + r * 32 + 2 * ((k + r) & 15)];
                        acc = fma2(ad, fp[k], acc);
                    }
                    *(u64*)&FC[(i * 16 + r) * FCS + 2 * cp] = acc;
                }
            }
        }
    }
    __syncthreads();

    // ---- Phase G1: depthwise -> DWSdup[i][2cm] (dup'd), packed over m ----
    float* DWSD = XD;   // [8][384]
    {
        const int i = t >> 5, lane = t & 31;
#pragma unroll
        for (int u = 0; u < 3; u++) {
            int c = lane + 32 * u;
            u64 acc = *(const u64*)&dwb[2 * c];
#pragma unroll
            for (int k = 0; k < 16; k++) {
                float v = FC[(i * 16 + k) * FCS + c];
                u64 wd = *(const u64*)&g_dwWd[(c * 16 + k) * 2];
                acc = fma2(dup2(v), wd, acc);
            }
            float2 f = unpk(acc);
            float4 st; st.x = f.x; st.y = f.x; st.z = f.y; st.w = f.y;
            *(float4*)&DWSD[i * 384 + 4 * c] = st;
        }
    }
    __syncthreads();

    // ---- Phase G2: out = end_g*(elu(dw @ pwW + pwb)*BNI) + end_be ----
    {
        const int i = t >> 5, lane = t & 31;
        const int ob = lane * 4;
        ulonglong2 bi = *(const ulonglong2*)&pwb[ob];
        u64 acc0 = bi.x, acc1 = bi.y;
#pragma unroll 4
        for (int j = 0; j < 192; j++) {
            u64 vd = *(const u64*)&DWSD[i * 384 + 2 * j];
            ulonglong2 w = *(const ulonglong2*)&pwW[j * 128 + ob];
            acc0 = fma2(vd, w.x, acc0);
            acc1 = fma2(vd, w.y, acc1);
        }
        float2 f0 = unpk(acc0), f1 = unpk(acc1);
        float4 g4 = *(const float4*)&endg[ob];
        float4 e4 = *(const float4*)&endbe[ob];
        float4 o;
        o.x = g4.x * (eluf(f0.x) * BNI) + e4.x;
        o.y = g4.y * (eluf(f0.y) * BNI) + e4.y;
        o.z = g4.z * (eluf(f1.x) * BNI) + e4.z;
        o.w = g4.w * (eluf(f1.y) * BNI) + e4.w;
        *(float4*)&out[(size_t)(gp0 + i) * 128 + ob] = o;
    }
}

// ============================================================================
extern "C" void kernel_launch(void* const* d_in, const int* in_sizes, int n_in,
                              void* d_out, int out_size)
{
    const float* rep_pts = (const float*)d_in[0];
    const float* pts     = (const float*)d_in[1];
    const float* fts     = (const float*)d_in[2];
    const int*   pts_idx = (const int*)d_in[3];
    const float* d0W  = (const float*)d_in[4];
    const float* d0b  = (const float*)d_in[5];
    const float* d0g  = (const float*)d_in[6];
    const float* d0be = (const float*)d_in[7];
    const float* d1W  = (const float*)d_in[8];
    const float* d1b  = (const float*)d_in[9];
    const float* d1g  = (const float*)d_in[10];
    const float* d1be = (const float*)d_in[11];
    const float* d2W  = (const float*)d_in[12];
    const float* d2b  = (const float*)d_in[13];
    const float* d2g  = (const float*)d_in[14];
    const float* d2be = (const float*)d_in[15];
    const float* xcW  = (const float*)d_in[16];
    const float* xcb  = (const float*)d_in[17];
    const float* xd1W = (const float*)d_in[18];
    const float* xd1b = (const float*)d_in[19];
    const float* xd2W = (const float*)d_in[20];
    const float* xd2b = (const float*)d_in[21];
    const float* dwW  = (const float*)d_in[22];
    const float* dwb  = (const float*)d_in[23];
    const float* pwW  = (const float*)d_in[24];
    const float* pwb  = (const float*)d_in[25];
    const float* endg = (const float*)d_in[26];
    const float* endbe= (const float*)d_in[27];
    float* out = (float*)d_out;

    dup_weights<<<256, 256>>>(xd1W, xd2W, xcW, dwW);
    dense0_kernel<<<4096, 256>>>(fts, d0W, d0b, d0g, d0be);

    cudaFuncSetAttribute(xconv_kernel,
                         cudaFuncAttributeMaxDynamicSharedMemorySize, SMEM_B);
    xconv_kernel<<<32768 / TILEP, 256, SMEM_B>>>(
        rep_pts, pts, pts_idx,
        d1W, d1b, d1g, d1be, d2W, d2b, d2g, d2be,
        xcb, xd1b, xd2b,
        dwb, pwW, pwb, endg, endbe, out);
}

// round 4
// speedup vs baseline: 1.9552x; 1.9552x over previous
#include <cuda_runtime.h>
#include <math.h>

typedef unsigned long long u64;

// ---- problem dims ----
#define NB      32
#define NUMPTS  2048
#define PN      1024
#define KK      16
#define CIN     64
#define CHALF   64
#define CMID    32
#define CCAT    96
#define COUT    128
#define TILEP   8
#define FCS     100
#define BNI     0.9999950000374996f

// scratch: lifted features fts_l (N, NUM_PTS, 64)
__device__ float g_ftsl[NB * NUMPTS * CHALF];

__device__ __forceinline__ float eluf(float x) {
    return x > 0.0f ? x : expm1f(x);
}
__device__ __forceinline__ u64 fma2(u64 a, u64 b, u64 c) {
    u64 d; asm("fma.rn.f32x2 %0,%1,%2,%3;" : "=l"(d) : "l"(a), "l"(b), "l"(c)); return d;
}
__device__ __forceinline__ u64 dup2(float x) {
    u64 d; asm("mov.b64 %0,{%1,%1};" : "=l"(d) : "f"(x)); return d;
}
__device__ __forceinline__ float2 unpk(u64 v) {
    float2 r; asm("mov.b64 {%0,%1},%2;" : "=f"(r.x), "=f"(r.y) : "l"(v)); return r;
}

// ============================================================================
// Kernel A: fts_l = d0_g * (elu(fts @ d0_W + d0_b) * BNI) + d0_be
// ============================================================================
__global__ void __launch_bounds__(256) dense0_kernel(
    const float* __restrict__ fts, const float* __restrict__ W,
    const float* __restrict__ b,   const float* __restrict__ g,
    const float* __restrict__ be)
{
    __shared__ float Ws[64 * 64];
    __shared__ float xs[16 * 64];
    const int t = threadIdx.x;
    const size_t row0 = (size_t)blockIdx.x * 16;

#pragma unroll
    for (int u = 0; u < 16; u++) Ws[t + 256 * u] = W[t + 256 * u];
    ((float4*)xs)[t] = ((const float4*)(fts + row0 * 64))[t];
    __syncthreads();

    const int r  = t >> 4;
    const int cb = (t & 15) * 4;
    u64 a0 = 0ull, a1 = 0ull;
#pragma unroll 8
    for (int k = 0; k < 64; k++) {
        u64 xd = dup2(xs[r * 64 + k]);
        ulonglong2 w = *(const ulonglong2*)&Ws[k * 64 + cb];
        a0 = fma2(xd, w.x, a0);
        a1 = fma2(xd, w.y, a1);
    }
    float2 f0 = unpk(a0), f1 = unpk(a1);
    float4 b4 = *(const float4*)&b[cb];
    float4 g4 = *(const float4*)&g[cb];
    float4 e4 = *(const float4*)&be[cb];
    float4 o;
    o.x = g4.x * (eluf(f0.x + b4.x) * BNI) + e4.x;
    o.y = g4.y * (eluf(f0.y + b4.y) * BNI) + e4.y;
    o.z = g4.z * (eluf(f1.x + b4.z) * BNI) + e4.z;
    o.w = g4.w * (eluf(f1.y + b4.w) * BNI) + e4.w;
    *(float4*)&g_ftsl[(row0 + r) * 64 + cb] = o;
}

// ============================================================================
// Kernel B: fused XConv. TILE_P=8, 256 threads, 2 CTAs/SM.
// Identical structure to the 815us version; phases B/C/D use point-pair
// packed fma.rn.f32x2 (a-pairs adjacent in PT / XA / XB layouts).
// smem layout (floats):
//   PT    [48][8]          @ 0       (transposed local coords)
//   XA    [256][8] / H-lo  @ 384     (2048) ; H = [32][128] spans XA+XB
//   XB    [256][8] / H-hi  @ 2432    (2048)
//   FC    [8][16][FCS]     @ 4480    (12800)
//   SIDX  @ 17280 (128)
//   d1W @17408(96) d1b @17504 d1g @17536 d1be @17568
//   d2W @17600(1024) d2b @18624 d2g @18656 d2be @18688
// total 18720 floats = 74880 B
// ============================================================================
#define SM_FLOATS 18720
#define SMEM_B    (SM_FLOATS * 4)

__global__ void __launch_bounds__(256, 2) xconv_kernel(
    const float* __restrict__ rep_pts, const float* __restrict__ pts,
    const int*   __restrict__ pts_idx,
    const float* __restrict__ d1W, const float* __restrict__ d1b,
    const float* __restrict__ d1g, const float* __restrict__ d1be,
    const float* __restrict__ d2W, const float* __restrict__ d2b,
    const float* __restrict__ d2g, const float* __restrict__ d2be,
    const float* __restrict__ xcW,  const float* __restrict__ xcb,
    const float* __restrict__ xd1W, const float* __restrict__ xd1b,
    const float* __restrict__ xd2W, const float* __restrict__ xd2b,
    const float* __restrict__ dwW,  const float* __restrict__ dwb,
    const float* __restrict__ pwW,  const float* __restrict__ pwb,
    const float* __restrict__ endg, const float* __restrict__ endbe,
    float* __restrict__ out)
{
    extern __shared__ float sm[];
    float* PT   = sm;            // [48][8]
    float* XA   = sm + 384;      // [256][8]
    float* XB   = sm + 2432;     // [256][8]
    float* H    = sm + 384;      // [32][128]  (E phase only)
    float* FC   = sm + 4480;     // [8][16][FCS]
    int*   SIDX = (int*)(sm + 17280);
    float* SD1W = sm + 17408; float* SD1B  = sm + 17504;
    float* SD1G = sm + 17536; float* SD1BE = sm + 17568;
    float* SD2W = sm + 17600; float* SD2B  = sm + 18624;
    float* SD2G = sm + 18656; float* SD2BE = sm + 18688;

    const int t   = threadIdx.x;
    const int gp0 = blockIdx.x * TILEP;
    const int n   = gp0 >> 10;

    // ---- load small weights + neighbor indices ----
    for (int u = t; u < 96 + 1024; u += 256) {
        if (u < 96) SD1W[u] = d1W[u];
        else        SD2W[u - 96] = d2W[u - 96];
    }
    if (t < 32) {
        SD1B[t] = d1b[t]; SD1G[t] = d1g[t]; SD1BE[t] = d1be[t];
        SD2B[t] = d2b[t]; SD2G[t] = d2g[t]; SD2BE[t] = d2be[t];
    }
    if (t < 128) SIDX[t] = pts_idx[(size_t)gp0 * 16 + t];
    __syncthreads();

    // ---- gather coords (transposed, centered) + gather lifted features ----
    if (t < 128) {
        int i = t >> 4, k = t & 15;
        int gi = SIDX[t];
        const float* pp = pts + ((size_t)n * NUMPTS + gi) * 3;
        const float* rp = rep_pts + (size_t)(gp0 + i) * 3;
        PT[( 0 + k) * 8 + i] = pp[0] - rp[0];
        PT[(16 + k) * 8 + i] = pp[1] - rp[1];
        PT[(32 + k) * 8 + i] = pp[2] - rp[2];
    }
    {
        int row = t >> 1, half = t & 1;          // 128 rows x 2 halves
        int gi = SIDX[row];
        const float4* src = (const float4*)(g_ftsl + ((size_t)n * NUMPTS + gi) * 64 + half * 32);
        float4* dst = (float4*)&FC[row * FCS + 32 + half * 32];
#pragma unroll
        for (int u = 0; u < 8; u++) dst[u] = src[u];
    }
    __syncthreads();

    // ---- E1: dense1 (3 -> 32) into H[c][row] ----
    {
        const int row = t & 127, hc = t >> 7;
        const int i = row >> 4, k = row & 15;
        float px = PT[k * 8 + i];
        float py = PT[(16 + k) * 8 + i];
        float pz = PT[(32 + k) * 8 + i];
#pragma unroll
        for (int u = 0; u < 16; u++) {
            int c = hc * 16 + u;
            float v = fmaf(px, SD1W[c], fmaf(py, SD1W[32 + c],
                      fmaf(pz, SD1W[64 + c], SD1B[c])));
            H[c * 128 + row] = SD1G[c] * (eluf(v) * BNI) + SD1BE[c];
        }
    }
    __syncthreads();

    // ---- E2: dense2 (32 -> 32) from H into FC[:, 0:32] ----
    {
        const int row = t & 127, hc = t >> 7;
        float acc[16];
#pragma unroll
        for (int u = 0; u < 16; u++) acc[u] = SD2B[hc * 16 + u];
#pragma unroll 4
        for (int c = 0; c < 32; c++) {
            float hv = H[c * 128 + row];
            const float4* w4 = (const float4*)&SD2W[c * 32 + hc * 16];
#pragma unroll
            for (int q4 = 0; q4 < 4; q4++) {
                float4 w = w4[q4];
                acc[q4 * 4 + 0] += hv * w.x; acc[q4 * 4 + 1] += hv * w.y;
                acc[q4 * 4 + 2] += hv * w.z; acc[q4 * 4 + 3] += hv * w.w;
            }
        }
#pragma unroll
        for (int u = 0; u < 16; u++) {
            int c2 = hc * 16 + u;
            FC[row * FCS + c2] = SD2G[c2] * (eluf(acc[u]) * BNI) + SD2BE[c2];
        }
    }
    __syncthreads();   // H region about to be overwritten by phase B

    // ---- Phase B: X0[q] = elu(sum_48 pls*xcW[q]) -> XA[q][i], packed pairs ----
    {
        const int q = t;
        u64 acc[4] = {0ull, 0ull, 0ull, 0ull};
        const float4* w4p = (const float4*)(xcW + q * 48);
#pragma unroll 4
        for (int k4 = 0; k4 < 12; k4++) {
            float4 w = w4p[k4];
            float wv[4] = {w.x, w.y, w.z, w.w};
#pragma unroll
            for (int u = 0; u < 4; u++) {
                u64 wd = dup2(wv[u]);
                int k = k4 * 4 + u;
                ulonglong2 a0 = *(const ulonglong2*)&PT[k * 8];
                ulonglong2 a1 = *(const ulonglong2*)&PT[k * 8 + 4];
                acc[0] = fma2(a0.x, wd, acc[0]);
                acc[1] = fma2(a0.y, wd, acc[1]);
                acc[2] = fma2(a1.x, wd, acc[2]);
                acc[3] = fma2(a1.y, wd, acc[3]);
            }
        }
        float b = xcb[q];
        float2 f0 = unpk(acc[0]), f1 = unpk(acc[1]);
        float2 f2 = unpk(acc[2]), f3 = unpk(acc[3]);
        float4 o0, o1;
        o0.x = eluf(f0.x + b); o0.y = eluf(f0.y + b);
        o0.z = eluf(f1.x + b); o0.w = eluf(f1.y + b);
        o1.x = eluf(f2.x + b); o1.y = eluf(f2.y + b);
        o1.z = eluf(f3.x + b); o1.w = eluf(f3.y + b);
        *(float4*)&XA[q * 8]     = o0;
        *(float4*)&XA[q * 8 + 4] = o1;
    }
    __syncthreads();

    // ---- Phase C: X1 = elu(X0 @ xd1W + b) -> XB[q][i], packed pairs ----
    {
        const int q = t;
        u64 acc[4] = {0ull, 0ull, 0ull, 0ull};
#pragma unroll 4
        for (int j = 0; j < 256; j++) {
            u64 wd = dup2(__ldg(&xd1W[j * 256 + q]));
            ulonglong2 a0 = *(const ulonglong2*)&XA[j * 8];
            ulonglong2 a1 = *(const ulonglong2*)&XA[j * 8 + 4];
            acc[0] = fma2(a0.x, wd, acc[0]);
            acc[1] = fma2(a0.y, wd, acc[1]);
            acc[2] = fma2(a1.x, wd, acc[2]);
            acc[3] = fma2(a1.y, wd, acc[3]);
        }
        float b = xd1b[q];
        float2 f0 = unpk(acc[0]), f1 = unpk(acc[1]);
        float2 f2 = unpk(acc[2]), f3 = unpk(acc[3]);
        float4 o0, o1;
        o0.x = eluf(f0.x + b); o0.y = eluf(f0.y + b);
        o0.z = eluf(f1.x + b); o0.w = eluf(f1.y + b);
        o1.x = eluf(f2.x + b); o1.y = eluf(f2.y + b);
        o1.z = eluf(f3.x + b); o1.w = eluf(f3.y + b);
        *(float4*)&XB[q * 8]     = o0;
        *(float4*)&XB[q * 8 + 4] = o1;
    }
    __syncthreads();

    // ---- Phase D: X2 = X1 @ xd2W + b -> XA as [8][256], packed pairs ----
    {
        const int q = t;
        u64 acc[4] = {0ull, 0ull, 0ull, 0ull};
#pragma unroll 4
        for (int j = 0; j < 256; j++) {
            u64 wd = dup2(__ldg(&xd2W[j * 256 + q]));
            ulonglong2 a0 = *(const ulonglong2*)&XB[j * 8];
            ulonglong2 a1 = *(const ulonglong2*)&XB[j * 8 + 4];
            acc[0] = fma2(a0.x, wd, acc[0]);
            acc[1] = fma2(a0.y, wd, acc[1]);
            acc[2] = fma2(a1.x, wd, acc[2]);
            acc[3] = fma2(a1.y, wd, acc[3]);
        }
        float b = xd2b[q];
        float2 f0 = unpk(acc[0]), f1 = unpk(acc[1]);
        float2 f2 = unpk(acc[2]), f3 = unpk(acc[3]);
        XA[0 * 256 + q] = f0.x + b;  XA[1 * 256 + q] = f0.y + b;
        XA[2 * 256 + q] = f1.x + b;  XA[3 * 256 + q] = f1.y + b;
        XA[4 * 256 + q] = f2.x + b;  XA[5 * 256 + q] = f2.y + b;
        XA[6 * 256 + q] = f3.x + b;  XA[7 * 256 + q] = f3.y + b;
    }
    __syncthreads();

    // ---- Phase F: fts_X = X2(16x16) @ FC(16x96), in place in FC ----
    {
        const int i = t >> 5, lane = t & 31;
        const float* X2 = &XA[i * 256];
#pragma unroll
        for (int u = 0; u < 3; u++) {
            int c = lane + 32 * u;
            float f[16];
#pragma unroll
            for (int cc = 0; cc < 16; cc++) f[cc] = FC[(i * 16 + cc) * FCS + c];
#pragma unroll
            for (int r = 0; r < 16; r++) {
                float acc = 0.f;
                const float4* xr = (const float4*)&X2[r * 16];
#pragma unroll
                for (int c4 = 0; c4 < 4; c4++) {
                    float4 xv = xr[c4];
                    acc += xv.x * f[c4 * 4] + xv.y * f[c4 * 4 + 1]
                         + xv.z * f[c4 * 4 + 2] + xv.w * f[c4 * 4 + 3];
                }
                FC[(i * 16 + r) * FCS + c] = acc;
            }
        }
    }
    __syncthreads();

    // ---- Phase G1: depthwise dw[cm] = sum_k ftsX[k][c]*dwW[c][m][k] + dwb ----
    float* DWS = XB;   // reuse as [8][256], first 192 valid
    {
        const int i = t >> 5, lane = t & 31;
#pragma unroll
        for (int u = 0; u < 6; u++) {
            int cm = lane + 32 * u;         // 0..191
            int c = cm >> 1, m = cm & 1;
            float w[16];
            const float4* wp = (const float4*)(dwW + c * 32 + m * 16);
            *(float4*)&w[0]  = wp[0]; *(float4*)&w[4]  = wp[1];
            *(float4*)&w[8]  = wp[2]; *(float4*)&w[12] = wp[3];
            float acc = dwb[cm];
#pragma unroll
            for (int k = 0; k < 16; k++) acc += FC[(i * 16 + k) * FCS + c] * w[k];
            DWS[i * 256 + cm] = acc;
        }
    }
    __syncthreads();

    // ---- Phase G2: out = end_g*(elu(dw @ pwW + pwb)*BNI) + end_be ----
    {
        const int i = t >> 5, lane = t & 31;
        const int ob = lane * 4;
        ulonglong2 bi = *(const ulonglong2*)&pwb[ob];
        u64 acc0 = bi.x, acc1 = bi.y;
#pragma unroll 4
        for (int j = 0; j < 192; j++) {
            u64 vd = dup2(DWS[i * 256 + j]);
            ulonglong2 w = *(const ulonglong2*)&pwW[j * 128 + ob];
            acc0 = fma2(vd, w.x, acc0);
            acc1 = fma2(vd, w.y, acc1);
        }
        float2 f0 = unpk(acc0), f1 = unpk(acc1);
        float4 g4 = *(const float4*)&endg[ob];
        float4 e4 = *(const float4*)&endbe[ob];
        float4 o;
        o.x = g4.x * (eluf(f0.x) * BNI) + e4.x;
        o.y = g4.y * (eluf(f0.y) * BNI) + e4.y;
        o.z = g4.z * (eluf(f1.x) * BNI) + e4.z;
        o.w = g4.w * (eluf(f1.y) * BNI) + e4.w;
        *(float4*)&out[(size_t)(gp0 + i) * 128 + ob] = o;
    }
}

// ============================================================================
extern "C" void kernel_launch(void* const* d_in, const int* in_sizes, int n_in,
                              void* d_out, int out_size)
{
    const float* rep_pts = (const float*)d_in[0];
    const float* pts     = (const float*)d_in[1];
    const float* fts     = (const float*)d_in[2];
    const int*   pts_idx = (const int*)d_in[3];
    const float* d0W  = (const float*)d_in[4];
    const float* d0b  = (const float*)d_in[5];
    const float* d0g  = (const float*)d_in[6];
    const float* d0be = (const float*)d_in[7];
    const float* d1W  = (const float*)d_in[8];
    const float* d1b  = (const float*)d_in[9];
    const float* d1g  = (const float*)d_in[10];
    const float* d1be = (const float*)d_in[11];
    const float* d2W  = (const float*)d_in[12];
    const float* d2b  = (const float*)d_in[13];
    const float* d2g  = (const float*)d_in[14];
    const float* d2be = (const float*)d_in[15];
    const float* xcW  = (const float*)d_in[16];
    const float* xcb  = (const float*)d_in[17];
    const float* xd1W = (const float*)d_in[18];
    const float* xd1b = (const float*)d_in[19];
    const float* xd2W = (const float*)d_in[20];
    const float* xd2b = (const float*)d_in[21];
    const float* dwW  = (const float*)d_in[22];
    const float* dwb  = (const float*)d_in[23];
    const float* pwW  = (const float*)d_in[24];
    const float* pwb  = (const float*)d_in[25];
    const float* endg = (const float*)d_in[26];
    const float* endbe= (const float*)d_in[27];
    float* out = (float*)d_out;

    dense0_kernel<<<4096, 256>>>(fts, d0W, d0b, d0g, d0be);

    cudaFuncSetAttribute(xconv_kernel,
                         cudaFuncAttributeMaxDynamicSharedMemorySize, SMEM_B);
    xconv_kernel<<<32768 / TILEP, 256, SMEM_B>>>(
        rep_pts, pts, pts_idx,
        d1W, d1b, d1g, d1be, d2W, d2b, d2g, d2be,
        xcW, xcb, xd1W, xd1b, xd2W, xd2b,
        dwW, dwb, pwW, pwb, endg, endbe, out);
}